// round 3
// baseline (speedup 1.0000x reference)
#include <cuda_runtime.h>

// LIF-LSTM cell, fused fp32 GEMM + spike epilogue.
//
// gates[b, j] = sum_k hx[b,k]*Wh[j,k] + sum_k x[b,k]*Wi[j,k] + bh[j] + bi[j]
//   j in [0,4096): gate g = j/1024, n = j%1024
// i,f,c,o = spike(gate) with spike(v) = (v >= 0.3)
// cy = f*cx + i*c ; hy = o * (cy >= 0.3)
// out = [hy (16384x1024) ; cy (16384x1024)]  (reference tuple order)
//
// Shapes (fixed): B=16384, ind=outd=1024, K_total=2048 (hx then x).
// Inputs (metadata order): x, hx, cx, Wh, bh, Wi, bi. All float32.

#define BM   128     // rows per block
#define BNN  32      // n-values per block (x4 gates => 128 effective N cols)
#define BK   16
#define TM   8       // rows per thread
#define NTHREADS 256

#define BATCH 16384
#define OUTD  1024
#define HALF_OUT (16384 * 1024)   // offset of cy in out

__global__ __launch_bounds__(NTHREADS, 2)
void lif_lstm_fused_kernel(const float* __restrict__ x,
                           const float* __restrict__ hx,
                           const float* __restrict__ cx,
                           const float* __restrict__ Wh,
                           const float* __restrict__ bh,
                           const float* __restrict__ Wi,
                           const float* __restrict__ bi,
                           float* __restrict__ out)
{
    __shared__ float As[BK][BM];        // [k][row]
    __shared__ float Bs[BK][4 * BNN];   // [k][g*32 + nl]

    const int row0 = blockIdx.x * BM;   // 128 M-tiles
    const int n0   = blockIdx.y * BNN;  // 32 N-tiles

    const int tid = threadIdx.x;
    const int ty  = tid >> 4;   // 0..15 -> row group
    const int tx  = tid & 15;   // 0..15 -> n group

    // acc[i][g*2 + jn] : row i, gate g, local n jn
    float acc[TM][8];
#pragma unroll
    for (int i = 0; i < TM; i++)
#pragma unroll
        for (int j = 0; j < 8; j++) acc[i][j] = 0.0f;

    // K loop over 2048 (first 1024 from hx/Wh, second 1024 from x/Wi).
    for (int k0 = 0; k0 < 2048; k0 += BK) {
        const bool first  = (k0 < 1024);
        const int  kloc   = first ? k0 : (k0 - 1024);
        const float* __restrict__ Asrc = first ? hx : x;
        const float* __restrict__ Wsrc = first ? Wh : Wi;

        // Load A tile: 128 rows x 16 k = 512 float4, 2 per thread.
#pragma unroll
        for (int l = 0; l < 2; l++) {
            int idx = tid * 2 + l;
            int r   = idx >> 2;
            int kq  = (idx & 3) * 4;
            float4 v = *(const float4*)(Asrc + (size_t)(row0 + r) * 1024 + kloc + kq);
            As[kq + 0][r] = v.x;
            As[kq + 1][r] = v.y;
            As[kq + 2][r] = v.z;
            As[kq + 3][r] = v.w;
        }
        // Load B tile: 128 cols (g*32+nl -> W row g*1024+n0+nl) x 16 k.
#pragma unroll
        for (int l = 0; l < 2; l++) {
            int idx = tid * 2 + l;
            int c   = idx >> 2;
            int kq  = (idx & 3) * 4;
            int g   = c >> 5;
            int nl  = c & 31;
            int jrow = g * 1024 + n0 + nl;
            float4 v = *(const float4*)(Wsrc + (size_t)jrow * 1024 + kloc + kq);
            Bs[kq + 0][c] = v.x;
            Bs[kq + 1][c] = v.y;
            Bs[kq + 2][c] = v.z;
            Bs[kq + 3][c] = v.w;
        }
        __syncthreads();

#pragma unroll
        for (int k = 0; k < BK; k++) {
            float a[TM];
#pragma unroll
            for (int i = 0; i < TM; i++) a[i] = As[k][ty * 8 + i];
            float b[8];
#pragma unroll
            for (int g = 0; g < 4; g++) {
                b[g * 2 + 0] = Bs[k][g * 32 + tx * 2 + 0];
                b[g * 2 + 1] = Bs[k][g * 32 + tx * 2 + 1];
            }
#pragma unroll
            for (int i = 0; i < TM; i++)
#pragma unroll
                for (int j = 0; j < 8; j++)
                    acc[i][j] = fmaf(a[i], b[j], acc[i][j]);
        }
        __syncthreads();
    }

    // Epilogue: biases, spikes, cy/hy, stores.
#pragma unroll
    for (int jn = 0; jn < 2; jn++) {
        const int n = n0 + tx * 2 + jn;
        const float bias_i = bh[0 * 1024 + n] + bi[0 * 1024 + n];
        const float bias_f = bh[1 * 1024 + n] + bi[1 * 1024 + n];
        const float bias_c = bh[2 * 1024 + n] + bi[2 * 1024 + n];
        const float bias_o = bh[3 * 1024 + n] + bi[3 * 1024 + n];
#pragma unroll
        for (int i = 0; i < TM; i++) {
            const int brow = row0 + ty * 8 + i;
            const float ig = acc[i][0 * 2 + jn] + bias_i;
            const float fg = acc[i][1 * 2 + jn] + bias_f;
            const float cg = acc[i][2 * 2 + jn] + bias_c;
            const float og = acc[i][3 * 2 + jn] + bias_o;
            const float ip = (ig >= 0.3f) ? 1.0f : 0.0f;
            const float fp = (fg >= 0.3f) ? 1.0f : 0.0f;
            const float cp = (cg >= 0.3f) ? 1.0f : 0.0f;
            const float op = (og >= 0.3f) ? 1.0f : 0.0f;
            const float cxv = cx[(size_t)brow * 1024 + n];
            const float cy  = fp * cxv + ip * cp;
            const float cyp = (cy >= 0.3f) ? 1.0f : 0.0f;
            const float hy  = op * cyp;
            out[(size_t)brow * 1024 + n]            = hy;
            out[HALF_OUT + (size_t)brow * 1024 + n] = cy;
        }
    }
}

extern "C" void kernel_launch(void* const* d_in, const int* in_sizes, int n_in,
                              void* d_out, int out_size)
{
    (void)in_sizes; (void)n_in; (void)out_size;
    const float* x  = (const float*)d_in[0];
    const float* hx = (const float*)d_in[1];
    const float* cx = (const float*)d_in[2];
    const float* Wh = (const float*)d_in[3];
    const float* bh = (const float*)d_in[4];
    const float* Wi = (const float*)d_in[5];
    const float* bi = (const float*)d_in[6];
    float* out = (float*)d_out;

    dim3 grid(BATCH / BM, OUTD / BNN);   // 128 x 32 = 4096 blocks
    dim3 block(NTHREADS);
    lif_lstm_fused_kernel<<<grid, block>>>(x, hx, cx, Wh, bh, Wi, bi, out);
}